// round 12
// baseline (speedup 1.0000x reference)
#include <cuda_runtime.h>
#include <cuda_fp16.h>

// EgoAttentionNetwork: B=8192, E=64, F_IN=7, D=64, H=4, HD=16
// Round-11: two batches per CTA stacked in the MMA M dimension (rows 0-31 =
// batch0, 32-63 = batch1): B-fragments amortize across batches. Layer0 also
// runs on HMMA (k16 over fp16-compacted x). Warp = (batch, head); V held in
// packed-fp16 registers across softmax on the fast path. Exact 2-chunk slow
// path when a batch has >32 active entities.

typedef unsigned int u32;

#define NTHR 256
#define FULLMASK 0xffffffffu
#define AXS 24     // Axh row stride in halves (48B: conflict-free ldsm)
#define AHS 72     // Ah0/Ah1 row stride in halves (144B: conflict-free ldsm)

__device__ uint2   dF0[256];     // oth_w0 B-fragments [nt(8)][lane], k padded to 16
__device__ uint2   dF1[1024];    // oth_w1 B-fragments [kt(4)][nt(8)][lane]
__device__ uint2   dFk[1024];    // Wk fragments
__device__ uint2   dFv[1024];    // Wv fragments
__device__ __half2 dW1ep[2048];  // ego_w1 k-pair packed [kp][d]
__device__ __half2 dWqp[2048];   // Wq k-pair packed
__device__ __half2 dWcp[2048];   // Wc k-pair packed

static __device__ __forceinline__ unsigned int f2h2(float a, float b) {
    __half2 h = __floats2half2_rn(a, b);
    return *reinterpret_cast<unsigned int*>(&h);
}
static __device__ __forceinline__ float2 h2f(unsigned int u) {
    __half2 h = *reinterpret_cast<__half2*>(&u);
    return __half22float2(h);
}
static __device__ __forceinline__ u32 s2u(const void* p) {
    return (u32)__cvta_generic_to_shared(p);
}
static __device__ __forceinline__ void ldsm4(u32* a, u32 addr) {
    asm volatile("ldmatrix.sync.aligned.m8n8.x4.shared.b16 {%0,%1,%2,%3}, [%4];"
                 : "=r"(a[0]), "=r"(a[1]), "=r"(a[2]), "=r"(a[3]) : "r"(addr));
}
static __device__ __forceinline__ void mma16816(
    float& c0, float& c1, float& c2, float& c3,
    const u32* a, u32 b0, u32 b1)
{
    asm volatile(
        "mma.sync.aligned.m16n8k16.row.col.f32.f16.f16.f32 "
        "{%0,%1,%2,%3}, {%4,%5,%6,%7}, {%8,%9}, {%0,%1,%2,%3};"
        : "+f"(c0), "+f"(c1), "+f"(c2), "+f"(c3)
        : "r"(a[0]), "r"(a[1]), "r"(a[2]), "r"(a[3]), "r"(b0), "r"(b1));
}

__device__ __forceinline__ u32 pkw(const float* W, int k, int n) {
    return f2h2(__ldg(W + k * 64 + n), __ldg(W + (k + 1) * 64 + n));
}
__device__ __forceinline__ u32 pkw7(const float* W, int k, int n) {
    float a = (k < 7) ? __ldg(W + k * 64 + n) : 0.f;
    float b = (k + 1 < 7) ? __ldg(W + (k + 1) * 64 + n) : 0.f;
    return f2h2(a, b);
}

__global__ void prep_weights(const float* __restrict__ oth_w0,
                             const float* __restrict__ oth_w1,
                             const float* __restrict__ Wk,
                             const float* __restrict__ Wv,
                             const float* __restrict__ ego_w1,
                             const float* __restrict__ Wq,
                             const float* __restrict__ Wc)
{
    const int i = blockIdx.x * 256 + threadIdx.x;   // 0..2047
    const int lane = i & 31;
    if (i < 256) {
        const int nt = i >> 5;
        const int n = nt * 8 + (lane >> 2);
        const int k = (lane & 3) * 2;
        dF0[i] = make_uint2(pkw7(oth_w0, k, n), pkw7(oth_w0, k + 8, n));
    }
    if (i < 1024) {
        const int nt = (i >> 5) & 7, kt = i >> 8;
        const int n = nt * 8 + (lane >> 2);
        const int k = kt * 16 + (lane & 3) * 2;
        dF1[i] = make_uint2(pkw(oth_w1, k, n), pkw(oth_w1, k + 8, n));
        dFk[i] = make_uint2(pkw(Wk, k, n),     pkw(Wk, k + 8, n));
        dFv[i] = make_uint2(pkw(Wv, k, n),     pkw(Wv, k + 8, n));
    }
    {
        const int kp = i >> 6, d = i & 63;
        const int k0 = 2 * kp * 64 + d, k1 = (2 * kp + 1) * 64 + d;
        dW1ep[i] = __floats2half2_rn(__ldg(ego_w1 + k0), __ldg(ego_w1 + k1));
        dWqp[i]  = __floats2half2_rn(__ldg(Wq + k0),     __ldg(Wq + k1));
        dWcp[i]  = __floats2half2_rn(__ldg(Wc + k0),     __ldg(Wc + k1));
    }
}

struct __align__(16) SmemT {
    __half Axh[128 * AXS];   // fp16 compacted x rows (k-padded to 16)
    __half Ah0[128 * AHS];   // hidden (layer0 out)
    __half Ah1[128 * AHS];   // input_all (layer1 out)
    float  sX[2 * 64 * 8];   // fp32 raw x (ballots + ego path + gather src)
    float  h0[2 * 64];
    float  sEgo[2 * 64];
    float  sQ[2 * 64];
    float  sO[2 * 64];
    float  sS[2 * 4 * 64];
    float  sP[2 * 4 * 64];
    int    sIdx[2 * 64];
    int    gnOth[2], gUni[2], gEgoA[2];
};

__global__ void __launch_bounds__(NTHR, 4)
ego_attn_kernel(const float* __restrict__ x,
                const float* __restrict__ ego_w0, const float* __restrict__ ego_b0,
                const float* __restrict__ ego_b1,
                const float* __restrict__ oth_b0, const float* __restrict__ oth_b1,
                float* __restrict__ out)
{
    extern __shared__ char raw[];
    SmemT& s = *reinterpret_cast<SmemT*>(raw);
    const int tid = threadIdx.x;
    const int lane = tid & 31;
    const int w = tid >> 5;
    const int g = w & 3;        // head = pair of n8 tiles
    const int mtp = w >> 2;     // batch this warp's M rows belong to
    const long b2 = (long)blockIdx.x * 2;
    const int col0 = (lane & 3) * 2;

    // ---- PH1: load x for both batches; init scores ----
    for (int idx = tid; idx < 896; idx += NTHR) {
        int bb = idx >= 448;
        int j = idx - bb * 448;
        int e = j / 7, f = j - e * 7;
        s.sX[bb * 512 + e * 8 + f] = __ldg(x + (b2 + bb) * 448 + j);
    }
    s.sS[tid] = -1e30f;
    s.sS[tid + 256] = -1e30f;
    __syncthreads();

    // ---- PH2: warps 0-1 compaction | warps 2-3 ego layer0 ----
    if (w < 2) {
        const int b = w;
        const float* sxb = s.sX + b * 512;
        int egoA = (sxb[0] >= 0.5f) ? 1 : 0;
        unsigned m1 = __ballot_sync(FULLMASK, (lane >= 1) && (sxb[lane * 8] >= 0.5f));
        unsigned m2 = __ballot_sync(FULLMASK, sxb[(lane + 32) * 8] >= 0.5f);
        int cnt = __popc(m1) + __popc(m2);
        unsigned lmask = (1u << lane) - 1u;
        int* idxb = s.sIdx + b * 64;
        if (cnt == 0 && !egoA) {
            idxb[lane] = lane + 1;
            if (lane < 31) idxb[lane + 32] = lane + 33;
            if (lane == 0) { s.gnOth[b] = 63; s.gUni[b] = 1; s.gEgoA[b] = egoA; }
        } else {
            if ((lane >= 1) && (m1 >> lane & 1u))
                idxb[__popc(m1 & lmask)] = lane;
            if (m2 >> lane & 1u)
                idxb[__popc(m1) + __popc(m2 & lmask)] = lane + 32;
            if (lane == 0) { s.gnOth[b] = cnt; s.gUni[b] = 0; s.gEgoA[b] = egoA; }
        }
    } else if (w < 4) {
        const int b = w - 2;
        const float* sxb = s.sX + b * 512;
        #pragma unroll
        for (int r = 0; r < 2; r++) {
            int d = lane + r * 32;
            float acc = __ldg(ego_b0 + d);
            #pragma unroll
            for (int f = 0; f < 7; f++)
                acc += sxb[f] * __ldg(ego_w0 + f * 64 + d);
            s.h0[b * 64 + d] = fmaxf(acc, 0.f);
        }
    }
    __syncthreads();

    int nOth[2], uniF[2], egoA[2], nTot[2], cEgo[2], egoRow[2];
    #pragma unroll
    for (int i = 0; i < 2; i++) {
        nOth[i] = s.gnOth[i]; uniF[i] = s.gUni[i]; egoA[i] = s.gEgoA[i];
        nTot[i] = nOth[i] + 1; cEgo[i] = nOth[i];
        egoRow[i] = 64 * (cEgo[i] >> 5) + 32 * i + (cEgo[i] & 31);
    }
    const int npass = (nTot[0] > 32 || nTot[1] > 32) ? 2 : 1;

    // ---- PH3: gather compacted x -> Axh fp16 | ego layer1 ----
    if (tid < 128) {
        const int row = tid;
        const int ch = row >> 6, b = (row >> 5) & 1, rl = row & 31;
        if (ch < npass) {
            const int e = 32 * ch + rl;
            __half2* dst = reinterpret_cast<__half2*>(s.Axh + row * AXS);
            const __half2 z2 = __floats2half2_rn(0.f, 0.f);
            if (e < nOth[b]) {
                const float* xr = s.sX + b * 512 + s.sIdx[b * 64 + e] * 8;
                dst[0] = __floats2half2_rn(xr[0], xr[1]);
                dst[1] = __floats2half2_rn(xr[2], xr[3]);
                dst[2] = __floats2half2_rn(xr[4], xr[5]);
                dst[3] = __floats2half2_rn(xr[6], 0.f);
                dst[4] = z2; dst[5] = z2; dst[6] = z2; dst[7] = z2;
            } else {
                #pragma unroll
                for (int i = 0; i < 8; i++) dst[i] = z2;
            }
        }
    } else if (tid >= 192) {
        const int b = (tid - 192) >> 5, dd = (tid - 192) & 31;
        #pragma unroll
        for (int r = 0; r < 2; r++) {
            const int d = dd + r * 32;
            float a0 = __ldg(ego_b1 + d), a1 = 0.f;
            #pragma unroll 8
            for (int kp = 0; kp < 32; kp++) {
                float2 wv = __half22float2(__ldg(&dW1ep[kp * 64 + d]));
                float2 hv = *reinterpret_cast<const float2*>(&s.h0[b * 64 + 2 * kp]);
                a0 += hv.x * wv.x;
                a1 += hv.y * wv.y;
            }
            s.sEgo[b * 64 + d] = fmaxf(a0 + a1, 0.f);
        }
    }
    __syncthreads();

    // ---- PH4: layer0 HMMA (k16): Axh -> Ah0 (bias+relu) ----
    for (int ch = 0; ch < npass; ch++) {
        const int mA = 64 * ch + 32 * mtp;
        u32 aA[4], aB[4];
        u32 base = s2u(s.Axh + (mA + (lane & 15)) * AXS + ((lane >> 4) << 3));
        ldsm4(aA, base);
        ldsm4(aB, base + 16 * AXS * 2);
        #pragma unroll
        for (int nt2 = 0; nt2 < 2; nt2++) {
            const int nt = g * 2 + nt2;
            const int cA = nt * 8 + col0;
            uint2 bf = __ldg(&dF0[nt * 32 + lane]);
            float bb0 = __ldg(oth_b0 + cA), bb1 = __ldg(oth_b0 + cA + 1);
            float c0 = bb0, c1 = bb1, c2 = bb0, c3 = bb1;
            float d0 = bb0, d1 = bb1, d2 = bb0, d3 = bb1;
            mma16816(c0, c1, c2, c3, aA, bf.x, bf.y);
            mma16816(d0, d1, d2, d3, aB, bf.x, bf.y);
            const int r = mA + (lane >> 2);
            *reinterpret_cast<__half2*>(&s.Ah0[r * AHS + cA]) =
                __floats2half2_rn(fmaxf(c0, 0.f), fmaxf(c1, 0.f));
            *reinterpret_cast<__half2*>(&s.Ah0[(r + 8) * AHS + cA]) =
                __floats2half2_rn(fmaxf(c2, 0.f), fmaxf(c3, 0.f));
            *reinterpret_cast<__half2*>(&s.Ah0[(r + 16) * AHS + cA]) =
                __floats2half2_rn(fmaxf(d0, 0.f), fmaxf(d1, 0.f));
            *reinterpret_cast<__half2*>(&s.Ah0[(r + 24) * AHS + cA]) =
                __floats2half2_rn(fmaxf(d2, 0.f), fmaxf(d3, 0.f));
        }
    }
    __syncthreads();

    // ---- PH5: layer1 HMMA: Ah0 -> Ah1 (bias+relu+ego patch); then q ----
    for (int ch = 0; ch < npass; ch++) {
        const int mA = 64 * ch + 32 * mtp;
        float C[2][2][4];
        #pragma unroll
        for (int nt2 = 0; nt2 < 2; nt2++) {
            const int cA = (g * 2 + nt2) * 8 + col0;
            float bb0 = __ldg(oth_b1 + cA), bb1 = __ldg(oth_b1 + cA + 1);
            C[0][nt2][0] = bb0; C[0][nt2][1] = bb1; C[0][nt2][2] = bb0; C[0][nt2][3] = bb1;
            C[1][nt2][0] = bb0; C[1][nt2][1] = bb1; C[1][nt2][2] = bb0; C[1][nt2][3] = bb1;
        }
        u32 base = s2u(s.Ah0 + (mA + (lane & 15)) * AHS + ((lane >> 4) << 3));
        #pragma unroll
        for (int kt = 0; kt < 4; kt++) {
            u32 aA[4], aB[4];
            ldsm4(aA, base + kt * 32);
            ldsm4(aB, base + 16 * AHS * 2 + kt * 32);
            #pragma unroll
            for (int nt2 = 0; nt2 < 2; nt2++) {
                uint2 bf = __ldg(&dF1[(kt * 8 + g * 2 + nt2) * 32 + lane]);
                mma16816(C[0][nt2][0], C[0][nt2][1], C[0][nt2][2], C[0][nt2][3],
                         aA, bf.x, bf.y);
                mma16816(C[1][nt2][0], C[1][nt2][1], C[1][nt2][2], C[1][nt2][3],
                         aB, bf.x, bf.y);
            }
        }
        #pragma unroll
        for (int mt2 = 0; mt2 < 2; mt2++) {
            const int r0 = mA + 16 * mt2 + (lane >> 2), r1 = r0 + 8;
            #pragma unroll
            for (int nt2 = 0; nt2 < 2; nt2++) {
                const int cA = (g * 2 + nt2) * 8 + col0;
                float c0 = fmaxf(C[mt2][nt2][0], 0.f);
                float c1 = fmaxf(C[mt2][nt2][1], 0.f);
                float c2 = fmaxf(C[mt2][nt2][2], 0.f);
                float c3 = fmaxf(C[mt2][nt2][3], 0.f);
                if (r0 == egoRow[mtp]) {
                    c0 = s.sEgo[mtp * 64 + cA]; c1 = s.sEgo[mtp * 64 + cA + 1];
                }
                if (r1 == egoRow[mtp]) {
                    c2 = s.sEgo[mtp * 64 + cA]; c3 = s.sEgo[mtp * 64 + cA + 1];
                }
                *reinterpret_cast<__half2*>(&s.Ah1[r0 * AHS + cA]) =
                    __floats2half2_rn(c0, c1);
                *reinterpret_cast<__half2*>(&s.Ah1[r1 * AHS + cA]) =
                    __floats2half2_rn(c2, c3);
            }
        }
    }
    if (tid < 128) {
        const int b = tid >> 6, d = tid & 63;
        float a0 = 0.f, a1 = 0.f;
        #pragma unroll 8
        for (int kp = 0; kp < 32; kp++) {
            float2 wv = __half22float2(__ldg(&dWqp[kp * 64 + d]));
            float2 ev = *reinterpret_cast<const float2*>(&s.sEgo[b * 64 + 2 * kp]);
            a0 += ev.x * wv.x;
            a1 += ev.y * wv.y;
        }
        s.sQ[b * 64 + d] = a0 + a1;
    }
    __syncthreads();

    // ---- PH6: K HMMA -> scores; fast path also computes V (held packed) ----
    for (int ch = 0; ch < npass; ch++) {
        const int mA = 64 * ch + 32 * mtp;
        float K[2][2][4] = {};
        u32 base = s2u(s.Ah1 + (mA + (lane & 15)) * AHS + ((lane >> 4) << 3));
        #pragma unroll
        for (int kt = 0; kt < 4; kt++) {
            u32 aA[4], aB[4];
            ldsm4(aA, base + kt * 32);
            ldsm4(aB, base + 16 * AHS * 2 + kt * 32);
            #pragma unroll
            for (int nt2 = 0; nt2 < 2; nt2++) {
                uint2 bf = __ldg(&dFk[(kt * 8 + g * 2 + nt2) * 32 + lane]);
                mma16816(K[0][nt2][0], K[0][nt2][1], K[0][nt2][2], K[0][nt2][3],
                         aA, bf.x, bf.y);
                mma16816(K[1][nt2][0], K[1][nt2][1], K[1][nt2][2], K[1][nt2][3],
                         aB, bf.x, bf.y);
            }
        }
        #pragma unroll
        for (int mt2 = 0; mt2 < 2; mt2++) {
            float p0 = 0.f, p1 = 0.f;
            #pragma unroll
            for (int nt2 = 0; nt2 < 2; nt2++) {
                const int cA = (g * 2 + nt2) * 8 + col0;
                float q0 = s.sQ[mtp * 64 + cA], q1 = s.sQ[mtp * 64 + cA + 1];
                p0 += K[mt2][nt2][0] * q0 + K[mt2][nt2][1] * q1;
                p1 += K[mt2][nt2][2] * q0 + K[mt2][nt2][3] * q1;
            }
            p0 += __shfl_xor_sync(FULLMASK, p0, 1);
            p1 += __shfl_xor_sync(FULLMASK, p1, 1);
            p0 += __shfl_xor_sync(FULLMASK, p0, 2);
            p1 += __shfl_xor_sync(FULLMASK, p1, 2);
            if ((lane & 3) == 0) {
                const int e0 = 32 * ch + 16 * mt2 + (lane >> 2), e1 = e0 + 8;
                bool a0 = uniF[mtp] ? (e0 < nTot[mtp])
                                    : ((e0 < nOth[mtp]) ||
                                       (e0 == cEgo[mtp] && egoA[mtp]));
                bool a1 = uniF[mtp] ? (e1 < nTot[mtp])
                                    : ((e1 < nOth[mtp]) ||
                                       (e1 == cEgo[mtp] && egoA[mtp]));
                s.sS[mtp * 256 + g * 64 + e0] = a0 ? p0 * 0.25f : -1e30f;
                s.sS[mtp * 256 + g * 64 + e1] = a1 ? p1 * 0.25f : -1e30f;
            }
        }
    }
    u32 vh[8];
    if (npass == 1) {
        float V[2][2][4] = {};
        const int mA = 32 * mtp;
        u32 base = s2u(s.Ah1 + (mA + (lane & 15)) * AHS + ((lane >> 4) << 3));
        #pragma unroll
        for (int kt = 0; kt < 4; kt++) {
            u32 aA[4], aB[4];
            ldsm4(aA, base + kt * 32);
            ldsm4(aB, base + 16 * AHS * 2 + kt * 32);
            #pragma unroll
            for (int nt2 = 0; nt2 < 2; nt2++) {
                uint2 bf = __ldg(&dFv[(kt * 8 + g * 2 + nt2) * 32 + lane]);
                mma16816(V[0][nt2][0], V[0][nt2][1], V[0][nt2][2], V[0][nt2][3],
                         aA, bf.x, bf.y);
                mma16816(V[1][nt2][0], V[1][nt2][1], V[1][nt2][2], V[1][nt2][3],
                         aB, bf.x, bf.y);
            }
        }
        #pragma unroll
        for (int mt2 = 0; mt2 < 2; mt2++)
            #pragma unroll
            for (int nt2 = 0; nt2 < 2; nt2++) {
                vh[(mt2 * 2 + nt2) * 2]     = f2h2(V[mt2][nt2][0], V[mt2][nt2][1]);
                vh[(mt2 * 2 + nt2) * 2 + 1] = f2h2(V[mt2][nt2][2], V[mt2][nt2][3]);
            }
    }
    __syncthreads();

    // ---- PH7: softmax (warp = (batch mtp, head g)) ----
    {
        const float* ss = s.sS + mtp * 256 + g * 64;
        float* pp = s.sP + mtp * 256 + g * 64;
        if (uniF[mtp]) {
            pp[lane] = 1.0f / 64.0f;
            pp[lane + 32] = 1.0f / 64.0f;
        } else {
            float s0 = ss[lane], s1 = ss[lane + 32];
            float m = fmaxf(s0, s1);
            #pragma unroll
            for (int off = 16; off; off >>= 1)
                m = fmaxf(m, __shfl_xor_sync(FULLMASK, m, off));
            float e0 = __expf(s0 - m), e1 = __expf(s1 - m);
            float sum = e0 + e1;
            #pragma unroll
            for (int off = 16; off; off >>= 1)
                sum += __shfl_xor_sync(FULLMASK, sum, off);
            float inv = 1.0f / sum;
            pp[lane] = e0 * inv;
            pp[lane + 32] = e1 * inv;
        }
    }
    __syncthreads();

    // ---- PH8: P.V reduce -> sO ----
    {
        float o[2][2] = {};
        if (npass == 1) {
            #pragma unroll
            for (int mt2 = 0; mt2 < 2; mt2++) {
                const int e0 = 16 * mt2 + (lane >> 2), e1 = e0 + 8;
                const float pr0 = s.sP[mtp * 256 + g * 64 + e0];
                const float pr1 = s.sP[mtp * 256 + g * 64 + e1];
                #pragma unroll
                for (int nt2 = 0; nt2 < 2; nt2++) {
                    float2 v01 = h2f(vh[(mt2 * 2 + nt2) * 2]);
                    float2 v23 = h2f(vh[(mt2 * 2 + nt2) * 2 + 1]);
                    o[nt2][0] += pr0 * v01.x + pr1 * v23.x;
                    o[nt2][1] += pr0 * v01.y + pr1 * v23.y;
                }
            }
        } else {
            for (int ch = 0; ch < 2; ch++) {
                const int mA = 64 * ch + 32 * mtp;
                float V[2][2][4] = {};
                u32 base = s2u(s.Ah1 + (mA + (lane & 15)) * AHS + ((lane >> 4) << 3));
                #pragma unroll
                for (int kt = 0; kt < 4; kt++) {
                    u32 aA[4], aB[4];
                    ldsm4(aA, base + kt * 32);
                    ldsm4(aB, base + 16 * AHS * 2 + kt * 32);
                    #pragma unroll
                    for (int nt2 = 0; nt2 < 2; nt2++) {
                        uint2 bf = __ldg(&dFv[(kt * 8 + g * 2 + nt2) * 32 + lane]);
                        mma16816(V[0][nt2][0], V[0][nt2][1], V[0][nt2][2], V[0][nt2][3],
                                 aA, bf.x, bf.y);
                        mma16816(V[1][nt2][0], V[1][nt2][1], V[1][nt2][2], V[1][nt2][3],
                                 aB, bf.x, bf.y);
                    }
                }
                #pragma unroll
                for (int mt2 = 0; mt2 < 2; mt2++) {
                    const int e0 = 32 * ch + 16 * mt2 + (lane >> 2), e1 = e0 + 8;
                    const float pr0 = s.sP[mtp * 256 + g * 64 + e0];
                    const float pr1 = s.sP[mtp * 256 + g * 64 + e1];
                    #pragma unroll
                    for (int nt2 = 0; nt2 < 2; nt2++) {
                        o[nt2][0] += pr0 * V[mt2][nt2][0] + pr1 * V[mt2][nt2][2];
                        o[nt2][1] += pr0 * V[mt2][nt2][1] + pr1 * V[mt2][nt2][3];
                    }
                }
            }
        }
        #pragma unroll
        for (int off = 4; off < 32; off <<= 1) {
            o[0][0] += __shfl_xor_sync(FULLMASK, o[0][0], off);
            o[0][1] += __shfl_xor_sync(FULLMASK, o[0][1], off);
            o[1][0] += __shfl_xor_sync(FULLMASK, o[1][0], off);
            o[1][1] += __shfl_xor_sync(FULLMASK, o[1][1], off);
        }
        if (lane < 4) {
            #pragma unroll
            for (int nt2 = 0; nt2 < 2; nt2++) {
                const int cA = (g * 2 + nt2) * 8 + lane * 2;
                s.sO[mtp * 64 + cA] = o[nt2][0];
                s.sO[mtp * 64 + cA + 1] = o[nt2][1];
            }
        }
    }
    __syncthreads();

    // ---- PH9: epilogue (out @ Wc + ego) * 0.5 ----
    if (tid < 128) {
        const int b = tid >> 6, d = tid & 63;
        float a0 = 0.f, a1 = 0.f;
        #pragma unroll 8
        for (int kp = 0; kp < 32; kp++) {
            float2 wv = __half22float2(__ldg(&dWcp[kp * 64 + d]));
            float2 ov = *reinterpret_cast<const float2*>(&s.sO[b * 64 + 2 * kp]);
            a0 += ov.x * wv.x;
            a1 += ov.y * wv.y;
        }
        out[(b2 + b) * 64 + d] = ((a0 + a1) + s.sEgo[b * 64 + d]) * 0.5f;
    }
}

extern "C" void kernel_launch(void* const* d_in, const int* in_sizes, int n_in,
                              void* d_out, int out_size) {
    (void)in_sizes; (void)n_in; (void)out_size;
    const float* x      = (const float*)d_in[0];
    const float* ego_w0 = (const float*)d_in[1];
    const float* ego_b0 = (const float*)d_in[2];
    const float* ego_w1 = (const float*)d_in[3];
    const float* ego_b1 = (const float*)d_in[4];
    const float* oth_w0 = (const float*)d_in[5];
    const float* oth_b0 = (const float*)d_in[6];
    const float* oth_w1 = (const float*)d_in[7];
    const float* oth_b1 = (const float*)d_in[8];
    const float* Wk     = (const float*)d_in[9];
    const float* Wv     = (const float*)d_in[10];
    const float* Wq     = (const float*)d_in[11];
    const float* Wc     = (const float*)d_in[12];
    float* out = (float*)d_out;

    const int smem = (int)sizeof(SmemT);
    cudaFuncSetAttribute(ego_attn_kernel,
                         cudaFuncAttributeMaxDynamicSharedMemorySize, smem);
    prep_weights<<<8, 256>>>(oth_w0, oth_w1, Wk, Wv, ego_w1, Wq, Wc);
    ego_attn_kernel<<<4096, NTHR, smem>>>(x, ego_w0, ego_b0, ego_b1,
                                          oth_b0, oth_b1, out);
}

// round 13
// speedup vs baseline: 1.4841x; 1.4841x over previous
#include <cuda_runtime.h>
#include <cuda_fp16.h>

// EgoAttentionNetwork: B=8192, E=64, F_IN=7, D=64, H=4, HD=16
// Round-12 = Round-10 (best: 78.6us; 1 batch/CTA, HMMA GEMMs, fused K+V with
// V in registers across softmax) + layer0 moved to HMMA (fp16-compacted x,
// one k16 MMA pass) replacing the scalar 7-FMA gather loops.

typedef unsigned int u32;

#define NTHR 256
#define FULLMASK 0xffffffffu
#define AXS 24     // Axh row stride in halves (48B: conflict-free ldsm)
#define AHS 72     // Ah0/Ah1 row stride in halves (144B)

__device__ uint2   dF0[256];     // oth_w0 B-fragments [nt(8)][lane], k padded to 16
__device__ uint2   dF1[1024];    // oth_w1 B-fragments [kt(4)][nt(8)][lane]
__device__ uint2   dFk[1024];    // Wk fragments
__device__ uint2   dFv[1024];    // Wv fragments
__device__ __half2 dW1ep[2048];  // ego_w1 k-pair packed
__device__ __half2 dWqp[2048];   // Wq k-pair packed
__device__ __half2 dWcp[2048];   // Wc k-pair packed

static __device__ __forceinline__ unsigned int f2h2(float a, float b) {
    __half2 h = __floats2half2_rn(a, b);
    return *reinterpret_cast<unsigned int*>(&h);
}
static __device__ __forceinline__ float2 h2f(unsigned int u) {
    __half2 h = *reinterpret_cast<__half2*>(&u);
    return __half22float2(h);
}
static __device__ __forceinline__ u32 s2u(const void* p) {
    return (u32)__cvta_generic_to_shared(p);
}
static __device__ __forceinline__ void ldsm4(u32* a, u32 addr) {
    asm volatile("ldmatrix.sync.aligned.m8n8.x4.shared.b16 {%0,%1,%2,%3}, [%4];"
                 : "=r"(a[0]), "=r"(a[1]), "=r"(a[2]), "=r"(a[3]) : "r"(addr));
}
static __device__ __forceinline__ void mma16816(
    float& c0, float& c1, float& c2, float& c3,
    const u32* a, u32 b0, u32 b1)
{
    asm volatile(
        "mma.sync.aligned.m16n8k16.row.col.f32.f16.f16.f32 "
        "{%0,%1,%2,%3}, {%4,%5,%6,%7}, {%8,%9}, {%0,%1,%2,%3};"
        : "+f"(c0), "+f"(c1), "+f"(c2), "+f"(c3)
        : "r"(a[0]), "r"(a[1]), "r"(a[2]), "r"(a[3]), "r"(b0), "r"(b1));
}

__device__ __forceinline__ u32 pkw(const float* W, int k, int n) {
    return f2h2(__ldg(W + k * 64 + n), __ldg(W + (k + 1) * 64 + n));
}
__device__ __forceinline__ u32 pkw7(const float* W, int k, int n) {
    float a = (k < 7) ? __ldg(W + k * 64 + n) : 0.f;
    float b = (k + 1 < 7) ? __ldg(W + (k + 1) * 64 + n) : 0.f;
    return f2h2(a, b);
}

__global__ void prep_weights(const float* __restrict__ oth_w0,
                             const float* __restrict__ oth_w1,
                             const float* __restrict__ Wk,
                             const float* __restrict__ Wv,
                             const float* __restrict__ ego_w1,
                             const float* __restrict__ Wq,
                             const float* __restrict__ Wc)
{
    const int i = blockIdx.x * 256 + threadIdx.x;   // 0..2047
    const int lane = i & 31;
    if (i < 256) {
        const int nt = i >> 5;
        const int n = nt * 8 + (lane >> 2);
        const int k = (lane & 3) * 2;
        dF0[i] = make_uint2(pkw7(oth_w0, k, n), pkw7(oth_w0, k + 8, n));
    }
    if (i < 1024) {
        const int nt = (i >> 5) & 7, kt = i >> 8;
        const int n = nt * 8 + (lane >> 2);
        const int k = kt * 16 + (lane & 3) * 2;
        dF1[i] = make_uint2(pkw(oth_w1, k, n), pkw(oth_w1, k + 8, n));
        dFk[i] = make_uint2(pkw(Wk, k, n),     pkw(Wk, k + 8, n));
        dFv[i] = make_uint2(pkw(Wv, k, n),     pkw(Wv, k + 8, n));
    }
    {
        const int kp = i >> 6, d = i & 63;
        const int k0 = 2 * kp * 64 + d, k1 = (2 * kp + 1) * 64 + d;
        dW1ep[i] = __floats2half2_rn(__ldg(ego_w1 + k0), __ldg(ego_w1 + k1));
        dWqp[i]  = __floats2half2_rn(__ldg(Wq + k0),     __ldg(Wq + k1));
        dWcp[i]  = __floats2half2_rn(__ldg(Wc + k0),     __ldg(Wc + k1));
    }
}

struct __align__(16) SmemT {
    __half Axh[64 * AXS];    // fp16 compacted x rows (k padded to 16)
    __half Ah0[64 * AHS];    // hidden (layer0 out)
    __half Ah1[64 * AHS];    // input_all (layer1 out)
    float  sX[64 * 8];       // fp32 raw x
    float  h0[64];
    float  sEgo[64];
    float  sQ[64];
    float  sO[64];
    float  sS[256];
    float  sP[256];
    int    sIdx[64];
    int    nOth, uniformF, egoAct;
};

__device__ __forceinline__ void softmax_phase(SmemT& s, int uniformF, int tid) {
    if (tid < 128) {
        const int h = tid >> 5, ln = tid & 31;
        if (uniformF) {
            const float p = 1.0f / 64.0f;
            s.sP[h * 64 + ln] = p;
            s.sP[h * 64 + ln + 32] = p;
        } else {
            float s0 = s.sS[h * 64 + ln];
            float s1 = s.sS[h * 64 + ln + 32];
            float m = fmaxf(s0, s1);
            #pragma unroll
            for (int off = 16; off; off >>= 1)
                m = fmaxf(m, __shfl_xor_sync(FULLMASK, m, off));
            float e0 = __expf(s0 - m);
            float e1 = __expf(s1 - m);
            float sum = e0 + e1;
            #pragma unroll
            for (int off = 16; off; off >>= 1)
                sum += __shfl_xor_sync(FULLMASK, sum, off);
            float inv = 1.0f / sum;
            s.sP[h * 64 + ln] = e0 * inv;
            s.sP[h * 64 + ln + 32] = e1 * inv;
        }
    }
}

__global__ void __launch_bounds__(NTHR, 4)
ego_attn_kernel(const float* __restrict__ x,
                const float* __restrict__ ego_w0, const float* __restrict__ ego_b0,
                const float* __restrict__ ego_b1,
                const float* __restrict__ oth_b0, const float* __restrict__ oth_b1,
                float* __restrict__ out)
{
    __shared__ SmemT s;
    const int tid = threadIdx.x;
    const int lane = tid & 31;
    const int w = tid >> 5;
    const int mt = w & 1;        // m16 tile within a 32-row pass
    const int g = w >> 1;        // head (= pair of n8 tiles)
    const long b = blockIdx.x;
    const float* xb = x + b * 448;
    const int col0 = (lane & 3) * 2;

    // ---- PH1: load x; init score/out buffers ----
    for (int idx = tid; idx < 448; idx += NTHR) {
        int e = idx / 7, f = idx - (idx / 7) * 7;
        s.sX[e * 8 + f] = __ldg(xb + idx);
    }
    s.sS[tid] = -1e30f;
    if (tid < 64) s.sO[tid] = 0.f;
    __syncthreads();

    // ---- PH2: compaction (warp0) | ego layer0 (warp1) ----
    if (tid < 32) {
        int egoA = (s.sX[0] >= 0.5f) ? 1 : 0;
        unsigned m1 = __ballot_sync(FULLMASK, (lane >= 1) && (s.sX[lane * 8] >= 0.5f));
        unsigned m2 = __ballot_sync(FULLMASK, s.sX[(lane + 32) * 8] >= 0.5f);
        int cnt = __popc(m1) + __popc(m2);
        unsigned lmask = (1u << lane) - 1u;
        if (cnt == 0 && !egoA) {
            s.sIdx[lane] = lane + 1;
            if (lane < 31) s.sIdx[lane + 32] = lane + 33;
            if (lane == 0) { s.nOth = 63; s.uniformF = 1; s.egoAct = egoA; }
        } else {
            if ((lane >= 1) && (m1 >> lane & 1u))
                s.sIdx[__popc(m1 & lmask)] = lane;
            if (m2 >> lane & 1u)
                s.sIdx[__popc(m1) + __popc(m2 & lmask)] = lane + 32;
            if (lane == 0) { s.nOth = cnt; s.uniformF = 0; s.egoAct = egoA; }
        }
    } else if (tid < 64) {
        const int ln = tid - 32;
        #pragma unroll
        for (int r = 0; r < 2; r++) {
            int d = ln + r * 32;
            float acc = __ldg(ego_b0 + d);
            #pragma unroll
            for (int f = 0; f < 7; f++)
                acc += s.sX[f] * __ldg(ego_w0 + f * 64 + d);
            s.h0[d] = fmaxf(acc, 0.f);
        }
    }
    __syncthreads();

    const int nOth = s.nOth;
    const int uniformF = s.uniformF;
    const int egoAct = s.egoAct;
    const int cEgo = nOth;
    const int nTot = nOth + 1;
    const int Mpad = (nTot <= 32) ? 32 : 64;
    const int npass = Mpad >> 5;

    // ---- PH3: gather compacted x -> Axh fp16 (thr 0-63) | ego layer1 ----
    if (tid < 64) {
        const int row = tid;
        if (row < Mpad) {
            __half2* dst = reinterpret_cast<__half2*>(s.Axh + row * AXS);
            const __half2 z2 = __floats2half2_rn(0.f, 0.f);
            if (row < nOth) {
                const float* xr = s.sX + s.sIdx[row] * 8;
                dst[0] = __floats2half2_rn(xr[0], xr[1]);
                dst[1] = __floats2half2_rn(xr[2], xr[3]);
                dst[2] = __floats2half2_rn(xr[4], xr[5]);
                dst[3] = __floats2half2_rn(xr[6], 0.f);
                dst[4] = z2; dst[5] = z2; dst[6] = z2; dst[7] = z2;
            } else {
                #pragma unroll
                for (int i = 0; i < 8; i++) dst[i] = z2;
            }
        }
    } else if (tid >= 192) {
        const int d = tid - 192;
        float a0 = __ldg(ego_b1 + d), a1 = 0.f;
        #pragma unroll 8
        for (int kp = 0; kp < 32; kp++) {
            float2 wv = __half22float2(__ldg(&dW1ep[kp * 64 + d]));
            float2 hv = *reinterpret_cast<const float2*>(&s.h0[2 * kp]);
            a0 += hv.x * wv.x;
            a1 += hv.y * wv.y;
        }
        s.sEgo[d] = fmaxf(a0 + a1, 0.f);
    }
    __syncthreads();

    // ---- PH4: layer0 HMMA (k16): Axh -> Ah0 (bias+relu) ----
    for (int mp = 0; mp < npass; mp++) {
        const int m_base = mp * 32 + mt * 16;
        u32 A[4];
        u32 ab = s2u(s.Axh + (m_base + (lane & 15)) * AXS + ((lane >> 4) << 3));
        ldsm4(A, ab);
        const int r0 = m_base + (lane >> 2), r1 = r0 + 8;
        #pragma unroll
        for (int nt2 = 0; nt2 < 2; nt2++) {
            const int nt = g * 2 + nt2;
            const int cA = nt * 8 + col0;
            uint2 bf = __ldg(&dF0[nt * 32 + lane]);
            float c0 = __ldg(oth_b0 + cA), c1 = __ldg(oth_b0 + cA + 1);
            float c2 = c0, c3 = c1;
            mma16816(c0, c1, c2, c3, A, bf.x, bf.y);
            *reinterpret_cast<__half2*>(&s.Ah0[r0 * AHS + cA]) =
                __floats2half2_rn(fmaxf(c0, 0.f), fmaxf(c1, 0.f));
            *reinterpret_cast<__half2*>(&s.Ah0[r1 * AHS + cA]) =
                __floats2half2_rn(fmaxf(c2, 0.f), fmaxf(c3, 0.f));
        }
    }
    __syncthreads();

    // ---- PH5: layer1 HMMA: Ah0 -> Ah1 (bias+relu+ego patch); then q ----
    for (int mp = 0; mp < npass; mp++) {
        const int m_base = mp * 32 + mt * 16;
        u32 A[4][4];
        u32 ab = s2u(s.Ah0 + (m_base + (lane & 15)) * AHS + ((lane >> 4) << 3));
        #pragma unroll
        for (int kt = 0; kt < 4; kt++) ldsm4(A[kt], ab + kt * 32);
        const int r0 = m_base + (lane >> 2), r1 = r0 + 8;
        #pragma unroll
        for (int nt2 = 0; nt2 < 2; nt2++) {
            const int nt = g * 2 + nt2;
            const int cA = nt * 8 + col0;
            float c0 = __ldg(oth_b1 + cA), c1 = __ldg(oth_b1 + cA + 1);
            float c2 = c0, c3 = c1;
            #pragma unroll
            for (int kt = 0; kt < 4; kt++) {
                uint2 bf = __ldg(&dF1[(kt * 8 + nt) * 32 + lane]);
                mma16816(c0, c1, c2, c3, A[kt], bf.x, bf.y);
            }
            c0 = fmaxf(c0, 0.f); c1 = fmaxf(c1, 0.f);
            c2 = fmaxf(c2, 0.f); c3 = fmaxf(c3, 0.f);
            if (r0 == cEgo) { c0 = s.sEgo[cA]; c1 = s.sEgo[cA + 1]; }
            if (r1 == cEgo) { c2 = s.sEgo[cA]; c3 = s.sEgo[cA + 1]; }
            *reinterpret_cast<__half2*>(&s.Ah1[r0 * AHS + cA]) =
                __floats2half2_rn(c0, c1);
            *reinterpret_cast<__half2*>(&s.Ah1[r1 * AHS + cA]) =
                __floats2half2_rn(c2, c3);
        }
    }
    if (tid < 64) {
        const int d = tid;
        float a0 = 0.f, a1 = 0.f;
        #pragma unroll 8
        for (int kp = 0; kp < 32; kp++) {
            float2 wv = __half22float2(__ldg(&dWqp[kp * 64 + d]));
            float2 ev = *reinterpret_cast<const float2*>(&s.sEgo[2 * kp]);
            a0 += ev.x * wv.x;
            a1 += ev.y * wv.y;
        }
        s.sQ[d] = a0 + a1;
    }
    __syncthreads();

    // ---- PH6..PH8: K GEMM -> scores -> softmax -> V GEMM -> P.V ----
    if (npass == 1) {
        // fast path: fused K+V MMAs, V kept in registers across softmax
        const int m_base = mt * 16;
        const int r0 = m_base + (lane >> 2), r1 = r0 + 8;
        u32 A[4][4];
        u32 ab = s2u(s.Ah1 + (m_base + (lane & 15)) * AHS + ((lane >> 4) << 3));
        #pragma unroll
        for (int kt = 0; kt < 4; kt++) ldsm4(A[kt], ab + kt * 32);
        float vV[2][4];
        float p0 = 0.f, p1 = 0.f;
        #pragma unroll
        for (int nt2 = 0; nt2 < 2; nt2++) {
            const int nt = g * 2 + nt2;
            const int cA = nt * 8 + col0;
            float k0 = 0.f, k1 = 0.f, k2 = 0.f, k3 = 0.f;
            float v0 = 0.f, v1 = 0.f, v2 = 0.f, v3 = 0.f;
            #pragma unroll
            for (int kt = 0; kt < 4; kt++) {
                uint2 bk = __ldg(&dFk[(kt * 8 + nt) * 32 + lane]);
                uint2 bv = __ldg(&dFv[(kt * 8 + nt) * 32 + lane]);
                mma16816(k0, k1, k2, k3, A[kt], bk.x, bk.y);
                mma16816(v0, v1, v2, v3, A[kt], bv.x, bv.y);
            }
            float q0 = s.sQ[cA], q1 = s.sQ[cA + 1];
            p0 += k0 * q0 + k1 * q1;
            p1 += k2 * q0 + k3 * q1;
            vV[nt2][0] = v0; vV[nt2][1] = v1; vV[nt2][2] = v2; vV[nt2][3] = v3;
        }
        p0 += __shfl_xor_sync(FULLMASK, p0, 1);
        p1 += __shfl_xor_sync(FULLMASK, p1, 1);
        p0 += __shfl_xor_sync(FULLMASK, p0, 2);
        p1 += __shfl_xor_sync(FULLMASK, p1, 2);
        if ((lane & 3) == 0) {
            bool a0 = uniformF ? (r0 < nTot)
                               : ((r0 < nOth) || (r0 == cEgo && egoAct));
            bool a1 = uniformF ? (r1 < nTot)
                               : ((r1 < nOth) || (r1 == cEgo && egoAct));
            s.sS[g * 64 + r0] = a0 ? p0 * 0.25f : -1e30f;
            s.sS[g * 64 + r1] = a1 ? p1 * 0.25f : -1e30f;
        }
        __syncthreads();
        softmax_phase(s, uniformF, tid);
        __syncthreads();
        const float pr0 = s.sP[g * 64 + r0];
        const float pr1 = s.sP[g * 64 + r1];
        #pragma unroll
        for (int nt2 = 0; nt2 < 2; nt2++) {
            const int cA = (g * 2 + nt2) * 8 + col0;
            float o0 = vV[nt2][0] * pr0 + vV[nt2][2] * pr1;
            float o1 = vV[nt2][1] * pr0 + vV[nt2][3] * pr1;
            #pragma unroll
            for (int off = 4; off < 32; off <<= 1) {
                o0 += __shfl_xor_sync(FULLMASK, o0, off);
                o1 += __shfl_xor_sync(FULLMASK, o1, off);
            }
            if (lane < 4) {
                atomicAdd(&s.sO[cA], o0);
                atomicAdd(&s.sO[cA + 1], o1);
            }
        }
        __syncthreads();
    } else {
        // slow path (nTot > 32, rare): K both passes, softmax, V both passes
        for (int mp = 0; mp < 2; mp++) {
            const int m_base = mp * 32 + mt * 16;
            const int r0 = m_base + (lane >> 2), r1 = r0 + 8;
            u32 A[4][4];
            u32 ab = s2u(s.Ah1 + (m_base + (lane & 15)) * AHS + ((lane >> 4) << 3));
            #pragma unroll
            for (int kt = 0; kt < 4; kt++) ldsm4(A[kt], ab + kt * 32);
            float p0 = 0.f, p1 = 0.f;
            #pragma unroll
            for (int nt2 = 0; nt2 < 2; nt2++) {
                const int nt = g * 2 + nt2;
                const int cA = nt * 8 + col0;
                float k0 = 0.f, k1 = 0.f, k2 = 0.f, k3 = 0.f;
                #pragma unroll
                for (int kt = 0; kt < 4; kt++) {
                    uint2 bk = __ldg(&dFk[(kt * 8 + nt) * 32 + lane]);
                    mma16816(k0, k1, k2, k3, A[kt], bk.x, bk.y);
                }
                float q0 = s.sQ[cA], q1 = s.sQ[cA + 1];
                p0 += k0 * q0 + k1 * q1;
                p1 += k2 * q0 + k3 * q1;
            }
            p0 += __shfl_xor_sync(FULLMASK, p0, 1);
            p1 += __shfl_xor_sync(FULLMASK, p1, 1);
            p0 += __shfl_xor_sync(FULLMASK, p0, 2);
            p1 += __shfl_xor_sync(FULLMASK, p1, 2);
            if ((lane & 3) == 0) {
                bool a0 = uniformF ? (r0 < nTot)
                                   : ((r0 < nOth) || (r0 == cEgo && egoAct));
                bool a1 = uniformF ? (r1 < nTot)
                                   : ((r1 < nOth) || (r1 == cEgo && egoAct));
                s.sS[g * 64 + r0] = a0 ? p0 * 0.25f : -1e30f;
                s.sS[g * 64 + r1] = a1 ? p1 * 0.25f : -1e30f;
            }
        }
        __syncthreads();
        softmax_phase(s, uniformF, tid);
        __syncthreads();
        for (int mp = 0; mp < 2; mp++) {
            const int m_base = mp * 32 + mt * 16;
            const int r0 = m_base + (lane >> 2), r1 = r0 + 8;
            u32 A[4][4];
            u32 ab = s2u(s.Ah1 + (m_base + (lane & 15)) * AHS + ((lane >> 4) << 3));
            #pragma unroll
            for (int kt = 0; kt < 4; kt++) ldsm4(A[kt], ab + kt * 32);
            const float pr0 = s.sP[g * 64 + r0];
            const float pr1 = s.sP[g * 64 + r1];
            #pragma unroll
            for (int nt2 = 0; nt2 < 2; nt2++) {
                const int nt = g * 2 + nt2;
                const int cA = nt * 8 + col0;
                float v0 = 0.f, v1 = 0.f, v2 = 0.f, v3 = 0.f;
                #pragma unroll
                for (int kt = 0; kt < 4; kt++) {
                    uint2 bv = __ldg(&dFv[(kt * 8 + nt) * 32 + lane]);
                    mma16816(v0, v1, v2, v3, A[kt], bv.x, bv.y);
                }
                float o0 = v0 * pr0 + v2 * pr1;
                float o1 = v1 * pr0 + v3 * pr1;
                #pragma unroll
                for (int off = 4; off < 32; off <<= 1) {
                    o0 += __shfl_xor_sync(FULLMASK, o0, off);
                    o1 += __shfl_xor_sync(FULLMASK, o1, off);
                }
                if (lane < 4) {
                    atomicAdd(&s.sO[cA], o0);
                    atomicAdd(&s.sO[cA + 1], o1);
                }
            }
        }
        __syncthreads();
    }

    // ---- PH9: epilogue (out @ Wc + ego) * 0.5 ----
    if (tid < 64) {
        const int d = tid;
        float a0 = 0.f, a1 = 0.f;
        #pragma unroll 8
        for (int kp = 0; kp < 32; kp++) {
            float2 wv = __half22float2(__ldg(&dWcp[kp * 64 + d]));
            float2 ov = *reinterpret_cast<const float2*>(&s.sO[2 * kp]);
            a0 += ov.x * wv.x;
            a1 += ov.y * wv.y;
        }
        out[b * 64 + d] = ((a0 + a1) + s.sEgo[d]) * 0.5f;
    }
}

extern "C" void kernel_launch(void* const* d_in, const int* in_sizes, int n_in,
                              void* d_out, int out_size) {
    (void)in_sizes; (void)n_in; (void)out_size;
    const float* x      = (const float*)d_in[0];
    const float* ego_w0 = (const float*)d_in[1];
    const float* ego_b0 = (const float*)d_in[2];
    const float* ego_w1 = (const float*)d_in[3];
    const float* ego_b1 = (const float*)d_in[4];
    const float* oth_w0 = (const float*)d_in[5];
    const float* oth_b0 = (const float*)d_in[6];
    const float* oth_w1 = (const float*)d_in[7];
    const float* oth_b1 = (const float*)d_in[8];
    const float* Wk     = (const float*)d_in[9];
    const float* Wv     = (const float*)d_in[10];
    const float* Wq     = (const float*)d_in[11];
    const float* Wc     = (const float*)d_in[12];
    float* out = (float*)d_out;

    prep_weights<<<8, 256>>>(oth_w0, oth_w1, Wk, Wv, ego_w1, Wq, Wc);
    ego_attn_kernel<<<8192, NTHR>>>(x, ego_w0, ego_b0, ego_b1,
                                    oth_b0, oth_b1, out);
}